// round 2
// baseline (speedup 1.0000x reference)
#include <cuda_runtime.h>
#include <math.h>

#define BB 8
#define NBOX 300
#define RSEL 36
#define CCH 256
#define IOU_THRS 0.7f
#define CONF_THRS 0.3f
#define GRIDP 14     // OUT*SR
#define NWORDS 10    // ceil(300/32)

__device__ float g_selBoxes[BB][RSEL][4];
__device__ int   g_selLv[BB][RSEL];
__device__ int   g_selValid[BB][RSEL];

__device__ __forceinline__ float neg_inf() { return __int_as_float(0xff800000); }

// ---------------------------------------------------------------------------
// Kernel 1: per-batch sort + NMS + top-R selection + level assignment
// ---------------------------------------------------------------------------
__global__ void select_kernel(const float* __restrict__ boxes,
                              const float* __restrict__ scores)
{
    const int b   = blockIdx.x;
    const int tid = threadIdx.x;

    __shared__ float s[NBOX];
    __shared__ float bx[NBOX][4];
    __shared__ unsigned char val[NBOX];
    __shared__ unsigned int sup[NBOX][NWORDS];
    __shared__ unsigned int keepW[NWORDS];

    // thresholded scores
    if (tid < NBOX) {
        float sc = scores[b * NBOX + tid];
        s[tid] = (sc > CONF_THRS) ? sc : neg_inf();
    }
    __syncthreads();

    // stable descending rank (ties broken by original index)
    if (tid < NBOX) {
        float mys = s[tid];
        int rank = 0;
        for (int k = 0; k < NBOX; k++) {
            float sk = s[k];
            rank += (sk > mys) || (sk == mys && k < tid);
        }
        const float* bp = boxes + (size_t)(b * NBOX + tid) * 4;
        bx[rank][0] = bp[0];
        bx[rank][1] = bp[1];
        bx[rank][2] = bp[2];
        bx[rank][3] = bp[3];
        val[rank] = (mys > CONF_THRS) ? 1 : 0;
    }
    __syncthreads();

    // suppression bitmasks: row i has bits j>i where IOU(i,j) > thr
    if (tid < NBOX) {
        const float ax1 = bx[tid][0], ay1 = bx[tid][1];
        const float ax2 = bx[tid][2], ay2 = bx[tid][3];
        const float areaA = __fmul_rn(__fsub_rn(ax2, ax1), __fsub_rn(ay2, ay1));
        for (int t = 0; t < NWORDS; t++) {
            unsigned int w = 0;
            const int j0 = t * 32;
            for (int jj = 0; jj < 32; jj++) {
                const int j = j0 + jj;
                if (j > tid && j < NBOX) {
                    float b1 = bx[j][0], b2 = bx[j][1], b3 = bx[j][2], b4 = bx[j][3];
                    float areaB = __fmul_rn(__fsub_rn(b3, b1), __fsub_rn(b4, b2));
                    float ltx = fmaxf(ax1, b1), lty = fmaxf(ay1, b2);
                    float rbx = fminf(ax2, b3), rby = fminf(ay2, b4);
                    float iw = fmaxf(__fsub_rn(rbx, ltx), 0.0f);
                    float ih = fmaxf(__fsub_rn(rby, lty), 0.0f);
                    float inter = __fmul_rn(iw, ih);
                    float den = __fadd_rn(__fsub_rn(__fadd_rn(areaA, areaB), inter), 1e-9f);
                    float iou = __fdiv_rn(inter, den);
                    if (iou > IOU_THRS) w |= (1u << jj);
                }
            }
            sup[tid][t] = w;
        }
    }

    // initial keep bits
    if (tid < NWORDS) {
        unsigned int w = 0;
        for (int jj = 0; jj < 32; jj++) {
            int j = tid * 32 + jj;
            if (j < NBOX && val[j]) w |= (1u << jj);
        }
        keepW[tid] = w;
    }
    __syncthreads();

    // serial greedy suppression (warp 0; keep bits live in lane registers)
    if (tid < 32) {
        unsigned int kw = (tid < NWORDS) ? keepW[tid] : 0u;
        for (int i = 0; i < NBOX; i++) {
            unsigned int word = __shfl_sync(0xffffffffu, kw, i >> 5);
            if ((word >> (i & 31)) & 1u) {
                unsigned int sm = (tid < NWORDS) ? sup[i][tid] : 0u;
                kw &= ~sm;
            }
        }
        if (tid < NWORDS) keepW[tid] = kw;
    }
    __syncthreads();

    // stable partition select: kept (in order) first, then dropped (in order)
    if (tid < NBOX) {
        const int w = tid >> 5, bit = tid & 31;
        int kept_before = 0;
        for (int t = 0; t < w; t++) kept_before += __popc(keepW[t]);
        kept_before += __popc(keepW[w] & ((1u << bit) - 1u));
        const bool mykeep = (keepW[w] >> bit) & 1u;
        int totKept = 0;
        for (int t = 0; t < NWORDS; t++) totKept += __popc(keepW[t]);

        int pos = mykeep ? kept_before : (totKept + (tid - kept_before));
        if (pos < RSEL) {
            float x1 = bx[tid][0], y1 = bx[tid][1];
            float x2 = bx[tid][2], y2 = bx[tid][3];
            g_selBoxes[b][pos][0] = x1;
            g_selBoxes[b][pos][1] = y1;
            g_selBoxes[b][pos][2] = x2;
            g_selBoxes[b][pos][3] = y2;
            g_selValid[b][pos] = mykeep ? 1 : 0;
            float dx = __fsub_rn(x2, x1), dy = __fsub_rn(y2, y1);
            float ss = __fadd_rn(__fmul_rn(dx, dx), __fmul_rn(dy, dy));
            float size = sqrtf(fmaxf(ss, 1e-12f));
            float t = floorf(__fadd_rn(4.0f, log2f(__fmul_rn(__fdiv_rn(size, 224.0f), 4.0f))));
            t = fminf(fmaxf(t, 2.0f), 5.0f);
            g_selLv[b][pos] = (int)t - 2;
        }
    }
}

// ---------------------------------------------------------------------------
// Kernel 2: ROI-align pooling with separable rank-1 weights.
// out[c] = (1/196) * sum_rows wy[r] * sum_x wxa[x] * f[c, row, x]
// Coalesced: each warp streams contiguous row spans of one channel plane.
// ---------------------------------------------------------------------------
__global__ void pool_kernel(const float* __restrict__ f0,
                            const float* __restrict__ f1,
                            const float* __restrict__ f2,
                            const float* __restrict__ f3,
                            float* __restrict__ out)
{
    const int b = blockIdx.y;
    const int r = blockIdx.x;
    const int tid = threadIdx.x;

    __shared__ float wxa[200];          // per-column weights (absolute x index)
    __shared__ int   srows[32];
    __shared__ float srwt[32];
    __shared__ int   sKr, sXmin, sXmax;

    float* op = out + ((size_t)(b * RSEL + r) * CCH);

    const int valid = g_selValid[b][r];
    if (!valid) { op[tid] = 0.0f; return; }

    const int lv = g_selLv[b][r];
    const int Hs[4] = {200, 100, 50, 25};
    const int H = Hs[lv];
    const int W = H;
    const float* fbase =
        (lv == 0 ? f0 : lv == 1 ? f1 : lv == 2 ? f2 : f3) + (size_t)b * CCH * H * W;

    if (tid < 200) wxa[tid] = 0.0f;
    __syncthreads();

    if (tid == 0) {
        const float x1 = g_selBoxes[b][r][0], y1 = g_selBoxes[b][r][1];
        const float x2 = g_selBoxes[b][r][2], y2 = g_selBoxes[b][r][3];
        const float rw = fmaxf(__fsub_rn(x2, x1), 1.0f);
        const float rh = fmaxf(__fsub_rn(y2, y1), 1.0f);

        // ---- x taps: dense column-weight array + tight span over nonzero taps
        int xmin = 0x7fffffff, xmax = -1;
        for (int k = 0; k < GRIDP; k++) {
            float g = (k + 0.5f) / (float)GRIDP;
            float X = __fadd_rn(x1, __fmul_rn(rw, g));
            float mx = (X < -1.0f || X > (float)W) ? 0.0f : 1.0f;
            float x = fminf(fmaxf(X, 0.0f), (float)(W - 1));
            int ix0 = (int)floorf(x);
            int ix1 = min(ix0 + 1, W - 1);
            float lx = __fsub_rn(x, (float)ix0);
            wxa[ix0] += __fmul_rn(1.0f - lx, mx);
            wxa[ix1] += __fmul_rn(lx, mx);
            if (mx > 0.0f) {
                if (ix0 < xmin) xmin = ix0;
                if (ix1 > xmax) xmax = ix1;
            }
        }

        // ---- y taps: deduped compact row list with accumulated weights
        int Kr = 0;
        for (int k = 0; k < GRIDP; k++) {
            float g = (k + 0.5f) / (float)GRIDP;
            float Y = __fadd_rn(y1, __fmul_rn(rh, g));
            float my = (Y < -1.0f || Y > (float)H) ? 0.0f : 1.0f;
            float y = fminf(fmaxf(Y, 0.0f), (float)(H - 1));
            int iy0 = (int)floorf(y);
            int iy1 = min(iy0 + 1, H - 1);
            float ly = __fsub_rn(y, (float)iy0);
            float w0 = __fmul_rn(1.0f - ly, my);
            float w1 = __fmul_rn(ly, my);
            for (int t = 0; t < 2; t++) {
                int   row = t ? iy1 : iy0;
                float wv  = t ? w1 : w0;
                if (wv == 0.0f) continue;
                int found = -1;
                for (int q = 0; q < Kr; q++)
                    if (srows[q] == row) { found = q; break; }
                if (found >= 0) srwt[found] += wv;
                else { srows[Kr] = row; srwt[Kr] = wv; Kr++; }
            }
        }
        if (xmax < xmin) Kr = 0;   // fully OOB in x
        sKr = Kr; sXmin = xmin; sXmax = xmax;
    }
    __syncthreads();

    const int Kr   = sKr;
    const int xmin = sXmin;
    const int xmax = sXmax;
    const int warp = tid >> 5;
    const int lane = tid & 31;

    for (int c = warp; c < CCH; c += 8) {
        const float* cp = fbase + (size_t)c * H * W;
        float acc = 0.0f;
        for (int j = 0; j < Kr; j++) {
            const float* rp = cp + srows[j] * W;
            float rsum = 0.0f;
            for (int x = xmin + lane; x <= xmax; x += 32)
                rsum += rp[x] * wxa[x];
            acc += srwt[j] * rsum;
        }
        #pragma unroll
        for (int o = 16; o > 0; o >>= 1)
            acc += __shfl_xor_sync(0xffffffffu, acc, o);
        if (lane == 0) op[c] = acc * (1.0f / 196.0f);
    }
}

// ---------------------------------------------------------------------------
extern "C" void kernel_launch(void* const* d_in, const int* in_sizes, int n_in,
                              void* d_out, int out_size)
{
    const float* boxes  = (const float*)d_in[0];
    const float* scores = (const float*)d_in[1];
    const float* f0     = (const float*)d_in[2];
    const float* f1     = (const float*)d_in[3];
    const float* f2     = (const float*)d_in[4];
    const float* f3     = (const float*)d_in[5];
    float* out = (float*)d_out;

    select_kernel<<<BB, 320>>>(boxes, scores);
    pool_kernel<<<dim3(RSEL, BB), 256>>>(f0, f1, f2, f3, out);
}

// round 3
// speedup vs baseline: 4.0524x; 4.0524x over previous
#include <cuda_runtime.h>
#include <math.h>

#define BB 8
#define NBOX 300
#define RSEL 36
#define CCH 256
#define NROI (BB * RSEL)
#define IOU_THRS 0.7f
#define CONF_THRS 0.3f
#define GRIDP 14     // OUT*SR
#define NWORDS 10    // ceil(300/32)
#define MAXROWS 28   // 14 samples x 2 taps
#define MAXSPAN 64   // proven span <= 54

__device__ float g_selBoxes[BB][RSEL][4];
__device__ int   g_selLv[BB][RSEL];
__device__ int   g_selValid[BB][RSEL];

// per-ROI pooling plan
__device__ float g_wx[NROI][MAXSPAN];
__device__ int   g_rows[NROI][MAXROWS];
__device__ float g_rwt[NROI][MAXROWS];
__device__ int4  g_meta[NROI];        // {Kr, xmin, xmax, lv}

__device__ __forceinline__ float neg_inf() { return __int_as_float(0xff800000); }

// ---------------------------------------------------------------------------
// Kernel 1: per-batch sort + NMS + top-R selection + level assignment
// ---------------------------------------------------------------------------
__global__ void select_kernel(const float* __restrict__ boxes,
                              const float* __restrict__ scores)
{
    const int b   = blockIdx.x;
    const int tid = threadIdx.x;

    __shared__ float s[NBOX];
    __shared__ float bx[NBOX][4];
    __shared__ unsigned char val[NBOX];
    __shared__ unsigned int sup[NBOX][NWORDS];
    __shared__ unsigned int keepW[NWORDS];

    if (tid < NBOX) {
        float sc = scores[b * NBOX + tid];
        s[tid] = (sc > CONF_THRS) ? sc : neg_inf();
    }
    __syncthreads();

    // stable descending rank
    if (tid < NBOX) {
        float mys = s[tid];
        int rank = 0;
        for (int k = 0; k < NBOX; k++) {
            float sk = s[k];
            rank += (sk > mys) || (sk == mys && k < tid);
        }
        const float* bp = boxes + (size_t)(b * NBOX + tid) * 4;
        bx[rank][0] = bp[0];
        bx[rank][1] = bp[1];
        bx[rank][2] = bp[2];
        bx[rank][3] = bp[3];
        val[rank] = (mys > CONF_THRS) ? 1 : 0;
    }
    __syncthreads();

    // suppression bitmasks
    if (tid < NBOX) {
        const float ax1 = bx[tid][0], ay1 = bx[tid][1];
        const float ax2 = bx[tid][2], ay2 = bx[tid][3];
        const float areaA = __fmul_rn(__fsub_rn(ax2, ax1), __fsub_rn(ay2, ay1));
        for (int t = 0; t < NWORDS; t++) {
            unsigned int w = 0;
            const int j0 = t * 32;
            for (int jj = 0; jj < 32; jj++) {
                const int j = j0 + jj;
                if (j > tid && j < NBOX) {
                    float b1 = bx[j][0], b2 = bx[j][1], b3 = bx[j][2], b4 = bx[j][3];
                    float areaB = __fmul_rn(__fsub_rn(b3, b1), __fsub_rn(b4, b2));
                    float ltx = fmaxf(ax1, b1), lty = fmaxf(ay1, b2);
                    float rbx = fminf(ax2, b3), rby = fminf(ay2, b4);
                    float iw = fmaxf(__fsub_rn(rbx, ltx), 0.0f);
                    float ih = fmaxf(__fsub_rn(rby, lty), 0.0f);
                    float inter = __fmul_rn(iw, ih);
                    float den = __fadd_rn(__fsub_rn(__fadd_rn(areaA, areaB), inter), 1e-9f);
                    float iou = __fdiv_rn(inter, den);
                    if (iou > IOU_THRS) w |= (1u << jj);
                }
            }
            sup[tid][t] = w;
        }
    }

    if (tid < NWORDS) {
        unsigned int w = 0;
        for (int jj = 0; jj < 32; jj++) {
            int j = tid * 32 + jj;
            if (j < NBOX && val[j]) w |= (1u << jj);
        }
        keepW[tid] = w;
    }
    __syncthreads();

    // serial greedy suppression (warp 0)
    if (tid < 32) {
        unsigned int kw = (tid < NWORDS) ? keepW[tid] : 0u;
        for (int i = 0; i < NBOX; i++) {
            unsigned int word = __shfl_sync(0xffffffffu, kw, i >> 5);
            if ((word >> (i & 31)) & 1u) {
                unsigned int sm = (tid < NWORDS) ? sup[i][tid] : 0u;
                kw &= ~sm;
            }
        }
        if (tid < NWORDS) keepW[tid] = kw;
    }
    __syncthreads();

    // stable partition select
    if (tid < NBOX) {
        const int w = tid >> 5, bit = tid & 31;
        int kept_before = 0;
        for (int t = 0; t < w; t++) kept_before += __popc(keepW[t]);
        kept_before += __popc(keepW[w] & ((1u << bit) - 1u));
        const bool mykeep = (keepW[w] >> bit) & 1u;
        int totKept = 0;
        for (int t = 0; t < NWORDS; t++) totKept += __popc(keepW[t]);

        int pos = mykeep ? kept_before : (totKept + (tid - kept_before));
        if (pos < RSEL) {
            float x1 = bx[tid][0], y1 = bx[tid][1];
            float x2 = bx[tid][2], y2 = bx[tid][3];
            g_selBoxes[b][pos][0] = x1;
            g_selBoxes[b][pos][1] = y1;
            g_selBoxes[b][pos][2] = x2;
            g_selBoxes[b][pos][3] = y2;
            g_selValid[b][pos] = mykeep ? 1 : 0;
            float dx = __fsub_rn(x2, x1), dy = __fsub_rn(y2, y1);
            float ss = __fadd_rn(__fmul_rn(dx, dx), __fmul_rn(dy, dy));
            float size = sqrtf(fmaxf(ss, 1e-12f));
            float t = floorf(__fadd_rn(4.0f, log2f(__fmul_rn(__fdiv_rn(size, 224.0f), 4.0f))));
            t = fminf(fmaxf(t, 2.0f), 5.0f);
            g_selLv[b][pos] = (int)t - 2;
        }
    }
}

// ---------------------------------------------------------------------------
// Kernel 1.5: per-ROI pooling plan (one thread per ROI)
// ---------------------------------------------------------------------------
__global__ void prep_kernel()
{
    const int roi = blockIdx.x * blockDim.x + threadIdx.x;
    if (roi >= NROI) return;
    const int b = roi / RSEL, r = roi % RSEL;

    float wx[MAXSPAN];
    #pragma unroll
    for (int i = 0; i < MAXSPAN; i++) wx[i] = 0.0f;

    int Kr = 0, xmin = 0, xmax = -1;
    const int lv = g_selLv[b][r];
    int rows[MAXROWS];
    float rwt[MAXROWS];

    if (g_selValid[b][r]) {
        const int Hs[4] = {200, 100, 50, 25};
        const int H = Hs[lv], W = H;
        const float x1 = g_selBoxes[b][r][0], y1 = g_selBoxes[b][r][1];
        const float x2 = g_selBoxes[b][r][2], y2 = g_selBoxes[b][r][3];
        const float rw = fmaxf(__fsub_rn(x2, x1), 1.0f);
        const float rh = fmaxf(__fsub_rn(y2, y1), 1.0f);

        // x taps -> tight span
        int xm = 0x7fffffff, xM = -1;
        float wdense[200 < MAXSPAN ? MAXSPAN : 200]; // temp over absolute x
        // two-pass: first find span, then fill relative weights
        int ix0s[GRIDP], ix1s[GRIDP];
        float lxs[GRIDP], mxs[GRIDP];
        for (int k = 0; k < GRIDP; k++) {
            float g = (k + 0.5f) / (float)GRIDP;
            float X = __fadd_rn(x1, __fmul_rn(rw, g));
            float mx = (X < -1.0f || X > (float)W) ? 0.0f : 1.0f;
            float x = fminf(fmaxf(X, 0.0f), (float)(W - 1));
            int i0 = (int)floorf(x);
            int i1 = min(i0 + 1, W - 1);
            ix0s[k] = i0; ix1s[k] = i1;
            lxs[k] = __fsub_rn(x, (float)i0); mxs[k] = mx;
            if (mx > 0.0f) { if (i0 < xm) xm = i0; if (i1 > xM) xM = i1; }
        }
        (void)wdense;
        if (xM >= xm && (xM - xm) < MAXSPAN) {
            for (int k = 0; k < GRIDP; k++) {
                if (mxs[k] == 0.0f) continue;
                wx[ix0s[k] - xm] += __fmul_rn(1.0f - lxs[k], mxs[k]);
                wx[ix1s[k] - xm] += __fmul_rn(lxs[k], mxs[k]);
            }
            xmin = xm; xmax = xM;

            // y taps -> deduped compact row list
            for (int k = 0; k < GRIDP; k++) {
                float g = (k + 0.5f) / (float)GRIDP;
                float Y = __fadd_rn(y1, __fmul_rn(rh, g));
                float my = (Y < -1.0f || Y > (float)H) ? 0.0f : 1.0f;
                float y = fminf(fmaxf(Y, 0.0f), (float)(H - 1));
                int iy0 = (int)floorf(y);
                int iy1 = min(iy0 + 1, H - 1);
                float ly = __fsub_rn(y, (float)iy0);
                float w0 = __fmul_rn(1.0f - ly, my);
                float w1 = __fmul_rn(ly, my);
                for (int t = 0; t < 2; t++) {
                    int   row = t ? iy1 : iy0;
                    float wv  = t ? w1 : w0;
                    if (wv == 0.0f) continue;
                    int found = -1;
                    for (int q = 0; q < Kr; q++)
                        if (rows[q] == row) { found = q; break; }
                    if (found >= 0) rwt[found] += wv;
                    else if (Kr < MAXROWS) { rows[Kr] = row; rwt[Kr] = wv; Kr++; }
                }
            }
        }
    }

    for (int i = 0; i < MAXSPAN; i++) g_wx[roi][i] = wx[i];
    for (int i = 0; i < MAXROWS; i++) {
        g_rows[roi][i] = (i < Kr) ? rows[i] : 0;
        g_rwt[roi][i]  = (i < Kr) ? rwt[i]  : 0.0f;
    }
    g_meta[roi] = make_int4(Kr, xmin, xmax, lv);
}

// ---------------------------------------------------------------------------
// Kernel 2: pooling. One warp per (roi, channel). grid (RSEL, BB, 32).
// ---------------------------------------------------------------------------
__global__ void __launch_bounds__(256)
pool_kernel(const float* __restrict__ f0,
            const float* __restrict__ f1,
            const float* __restrict__ f2,
            const float* __restrict__ f3,
            float* __restrict__ out)
{
    const int r = blockIdx.x, b = blockIdx.y;
    const int roi = b * RSEL + r;
    const int tid = threadIdx.x;
    const int warp = tid >> 5, lane = tid & 31;

    __shared__ float swx[MAXSPAN];
    __shared__ int   srows[MAXROWS];
    __shared__ float srwt[MAXROWS];
    __shared__ int4  smeta;

    if (tid < MAXSPAN)                          swx[tid] = g_wx[roi][tid];
    else if (tid < MAXSPAN + MAXROWS)           srows[tid - MAXSPAN] = g_rows[roi][tid - MAXSPAN];
    else if (tid < MAXSPAN + 2 * MAXROWS)       srwt[tid - MAXSPAN - MAXROWS] = g_rwt[roi][tid - MAXSPAN - MAXROWS];
    else if (tid == MAXSPAN + 2 * MAXROWS)      smeta = g_meta[roi];
    __syncthreads();

    const int Kr   = smeta.x;
    const int xmin = smeta.y;
    const int xmax = smeta.z;
    const int lv   = smeta.w;

    const int Hs[4] = {200, 100, 50, 25};
    const int H = Hs[lv], W = H;
    const float* fbase =
        (lv == 0 ? f0 : lv == 1 ? f1 : lv == 2 ? f2 : f3) + (size_t)b * CCH * H * W;

    const int c = blockIdx.z * 8 + warp;
    const float* cp = fbase + (size_t)c * H * W;

    const int x0 = xmin + lane;
    const int x1 = x0 + 32;
    const bool a0 = (x0 <= xmax);
    const bool a1 = (x1 <= xmax);
    const float w0 = a0 ? swx[lane] : 0.0f;
    const float w1 = a1 ? swx[lane + 32] : 0.0f;

    float acc = 0.0f;
    #pragma unroll 4
    for (int j = 0; j < Kr; j++) {
        const float* rp = cp + srows[j] * W;
        float s = 0.0f;
        if (a0) s = rp[x0] * w0;
        if (a1) s += rp[x1] * w1;
        acc += srwt[j] * s;
    }

    #pragma unroll
    for (int o = 16; o > 0; o >>= 1)
        acc += __shfl_xor_sync(0xffffffffu, acc, o);

    if (lane == 0)
        out[(size_t)roi * CCH + c] = acc * (1.0f / 196.0f);
}

// ---------------------------------------------------------------------------
extern "C" void kernel_launch(void* const* d_in, const int* in_sizes, int n_in,
                              void* d_out, int out_size)
{
    const float* boxes  = (const float*)d_in[0];
    const float* scores = (const float*)d_in[1];
    const float* f0     = (const float*)d_in[2];
    const float* f1     = (const float*)d_in[3];
    const float* f2     = (const float*)d_in[4];
    const float* f3     = (const float*)d_in[5];
    float* out = (float*)d_out;

    select_kernel<<<BB, 320>>>(boxes, scores);
    prep_kernel<<<(NROI + 127) / 128, 128>>>();
    pool_kernel<<<dim3(RSEL, BB, 32), 256>>>(f0, f1, f2, f3, out);
}

// round 5
// speedup vs baseline: 6.6808x; 1.6486x over previous
#include <cuda_runtime.h>
#include <math.h>

#define BB 8
#define NBOX 300
#define RSEL 36
#define CCH 256
#define NROI (BB * RSEL)
#define IOU_THRS 0.7f
#define CONF_THRS 0.3f
#define GRIDP 14     // OUT*SR
#define NWORDS 10    // ceil(300/32)
#define MAXROWS 28   // 14 samples x 2 taps
#define MAXSPAN 64

// ---- scratch (device globals; no allocs) ----
__device__ float4        g_sbox[BB][NBOX];           // sorted boxes
__device__ int           g_sval[BB][NBOX];           // valid flag (score > thr)
__device__ unsigned int  g_sup[BB][NWORDS][NBOX];    // word-major suppression bits

__device__ float g_wx[NROI][MAXSPAN];
__device__ int   g_rows[NROI][MAXROWS];
__device__ float g_rwt[NROI][MAXROWS];
__device__ int4  g_meta[NROI];                        // {Kr, xmin, xmax, lv}

__device__ __forceinline__ float neg_inf() { return __int_as_float(0xff800000); }

// ---------------------------------------------------------------------------
// Kernel A: per-batch stable descending sort (rank-based) -> global scratch
// ---------------------------------------------------------------------------
__global__ void sort_kernel(const float* __restrict__ boxes,
                            const float* __restrict__ scores)
{
    const int b   = blockIdx.x;
    const int tid = threadIdx.x;
    __shared__ float s[NBOX];

    if (tid < NBOX) {
        float sc = scores[b * NBOX + tid];
        s[tid] = (sc > CONF_THRS) ? sc : neg_inf();
    }
    __syncthreads();

    if (tid < NBOX) {
        const float mys = s[tid];
        int rank = 0;
        #pragma unroll 4
        for (int k = 0; k < NBOX; k++) {
            float sk = s[k];
            rank += (sk > mys) || (sk == mys && k < tid);
        }
        const float* bp = boxes + (size_t)(b * NBOX + tid) * 4;
        g_sbox[b][rank] = make_float4(bp[0], bp[1], bp[2], bp[3]);
        g_sval[b][rank] = (mys > CONF_THRS) ? 1 : 0;
    }
}

// ---------------------------------------------------------------------------
// Kernel B: suppression bitmask build. Block (t, b): word t for all rows i.
// ---------------------------------------------------------------------------
__global__ void iou_kernel()
{
    const int t = blockIdx.x;   // word index 0..9
    const int b = blockIdx.y;
    const int tid = threadIdx.x;

    __shared__ float4 sj[32];
    if (tid < 32) {
        int j = t * 32 + tid;
        sj[tid] = (j < NBOX) ? g_sbox[b][j] : make_float4(0.f, 0.f, 0.f, 0.f);
    }
    __syncthreads();

    if (tid < NBOX) {
        const float4 a = g_sbox[b][tid];
        const float areaA = __fmul_rn(__fsub_rn(a.z, a.x), __fsub_rn(a.w, a.y));
        unsigned int w = 0;
        const int j0 = t * 32;
        #pragma unroll 4
        for (int jj = 0; jj < 32; jj++) {
            const int j = j0 + jj;
            if (j > tid && j < NBOX) {
                float4 bb = sj[jj];
                float areaB = __fmul_rn(__fsub_rn(bb.z, bb.x), __fsub_rn(bb.w, bb.y));
                float ltx = fmaxf(a.x, bb.x), lty = fmaxf(a.y, bb.y);
                float rbx = fminf(a.z, bb.z), rby = fminf(a.w, bb.w);
                float iw = fmaxf(__fsub_rn(rbx, ltx), 0.0f);
                float ih = fmaxf(__fsub_rn(rby, lty), 0.0f);
                float inter = __fmul_rn(iw, ih);
                float den = __fadd_rn(__fsub_rn(__fadd_rn(areaA, areaB), inter), 1e-9f);
                float iou = __fdiv_rn(inter, den);
                if (iou > IOU_THRS) w |= (1u << jj);
            }
        }
        g_sup[b][t][tid] = w;
    }
}

// ---------------------------------------------------------------------------
// Kernel C: serial greedy NMS + stable partition + level + fused per-ROI prep
// ---------------------------------------------------------------------------
__global__ void nms_kernel()
{
    const int b   = blockIdx.x;
    const int tid = threadIdx.x;

    __shared__ unsigned int ssup[NWORDS * NBOX];   // [t][i]
    __shared__ unsigned int keepW[NWORDS];
    __shared__ float4 sselBox[RSEL];
    __shared__ int    sselLv[RSEL];
    __shared__ int    sselValid[RSEL];

    // stage suppression matrix (coalesced)
    const unsigned int* gsup = &g_sup[b][0][0];
    for (int k = tid; k < NWORDS * NBOX; k += blockDim.x)
        ssup[k] = gsup[k];

    // initial keep bits
    if (tid < NWORDS) {
        unsigned int w = 0;
        for (int jj = 0; jj < 32; jj++) {
            int j = tid * 32 + jj;
            if (j < NBOX && g_sval[b][j]) w |= (1u << jj);
        }
        keepW[tid] = w;
    }
    __syncthreads();

    // serial greedy pass: all 300 keep-bits live in one thread's registers
    if (tid == 0) {
        unsigned int kw[NWORDS];
        #pragma unroll
        for (int t = 0; t < NWORDS; t++) kw[t] = keepW[t];
        for (int i = 0; i < NBOX; i++) {
            if ((kw[i >> 5] >> (i & 31)) & 1u) {
                #pragma unroll
                for (int t = 0; t < NWORDS; t++)
                    kw[t] &= ~ssup[t * NBOX + i];
            }
        }
        #pragma unroll
        for (int t = 0; t < NWORDS; t++) keepW[t] = kw[t];
    }
    __syncthreads();

    // stable partition select: kept (in order) first, then dropped (in order)
    if (tid < NBOX) {
        const int w = tid >> 5, bit = tid & 31;
        int kept_before = 0;
        for (int t = 0; t < w; t++) kept_before += __popc(keepW[t]);
        kept_before += __popc(keepW[w] & ((1u << bit) - 1u));
        const bool mykeep = (keepW[w] >> bit) & 1u;
        int totKept = 0;
        for (int t = 0; t < NWORDS; t++) totKept += __popc(keepW[t]);

        int pos = mykeep ? kept_before : (totKept + (tid - kept_before));
        if (pos < RSEL) {
            float4 bx = g_sbox[b][tid];
            sselBox[pos]   = bx;
            sselValid[pos] = mykeep ? 1 : 0;
            float dx = __fsub_rn(bx.z, bx.x), dy = __fsub_rn(bx.w, bx.y);
            float ss = __fadd_rn(__fmul_rn(dx, dx), __fmul_rn(dy, dy));
            float size = sqrtf(fmaxf(ss, 1e-12f));
            float t = floorf(__fadd_rn(4.0f, log2f(__fmul_rn(__fdiv_rn(size, 224.0f), 4.0f))));
            t = fminf(fmaxf(t, 2.0f), 5.0f);
            sselLv[pos] = (int)t - 2;
        }
    }
    __syncthreads();

    // fused per-ROI pooling plan (threads 0..RSEL-1)
    if (tid < RSEL) {
        const int r   = tid;
        const int roi = b * RSEL + r;

        float wx[MAXSPAN];
        #pragma unroll
        for (int i = 0; i < MAXSPAN; i++) wx[i] = 0.0f;

        int Kr = 0, xmin = 0, xmax = -1;
        const int lv = sselLv[r];
        int   rows[MAXROWS];
        float rwt[MAXROWS];

        if (sselValid[r]) {
            const int Hs[4] = {200, 100, 50, 25};
            const int H = Hs[lv], W = H;
            const float4 bx = sselBox[r];
            const float rw = fmaxf(__fsub_rn(bx.z, bx.x), 1.0f);
            const float rh = fmaxf(__fsub_rn(bx.w, bx.y), 1.0f);

            int xm = 0x7fffffff, xM = -1;
            int ix0s[GRIDP], ix1s[GRIDP];
            float lxs[GRIDP], mxs[GRIDP];
            for (int k = 0; k < GRIDP; k++) {
                float g = (k + 0.5f) / (float)GRIDP;
                float X = __fadd_rn(bx.x, __fmul_rn(rw, g));
                float mx = (X < -1.0f || X > (float)W) ? 0.0f : 1.0f;
                float x = fminf(fmaxf(X, 0.0f), (float)(W - 1));
                int i0 = (int)floorf(x);
                int i1 = min(i0 + 1, W - 1);
                ix0s[k] = i0; ix1s[k] = i1;
                lxs[k] = __fsub_rn(x, (float)i0); mxs[k] = mx;
                if (mx > 0.0f) { if (i0 < xm) xm = i0; if (i1 > xM) xM = i1; }
            }
            if (xM >= xm && (xM - xm) < MAXSPAN) {
                for (int k = 0; k < GRIDP; k++) {
                    if (mxs[k] == 0.0f) continue;
                    wx[ix0s[k] - xm] += __fmul_rn(1.0f - lxs[k], mxs[k]);
                    wx[ix1s[k] - xm] += __fmul_rn(lxs[k], mxs[k]);
                }
                xmin = xm; xmax = xM;

                for (int k = 0; k < GRIDP; k++) {
                    float g = (k + 0.5f) / (float)GRIDP;
                    float Y = __fadd_rn(bx.y, __fmul_rn(rh, g));
                    float my = (Y < -1.0f || Y > (float)H) ? 0.0f : 1.0f;
                    float y = fminf(fmaxf(Y, 0.0f), (float)(H - 1));
                    int iy0 = (int)floorf(y);
                    int iy1 = min(iy0 + 1, H - 1);
                    float ly = __fsub_rn(y, (float)iy0);
                    float w0 = __fmul_rn(1.0f - ly, my);
                    float w1 = __fmul_rn(ly, my);
                    for (int tt = 0; tt < 2; tt++) {
                        int   row = tt ? iy1 : iy0;
                        float wv  = tt ? w1 : w0;
                        if (wv == 0.0f) continue;
                        int found = -1;
                        for (int q = 0; q < Kr; q++)
                            if (rows[q] == row) { found = q; break; }
                        if (found >= 0) rwt[found] += wv;
                        else if (Kr < MAXROWS) { rows[Kr] = row; rwt[Kr] = wv; Kr++; }
                    }
                }
            }
        }

        for (int i = 0; i < MAXSPAN; i++) g_wx[roi][i] = wx[i];
        for (int i = 0; i < MAXROWS; i++) {
            g_rows[roi][i] = (i < Kr) ? rows[i] : 0;
            g_rwt[roi][i]  = (i < Kr) ? rwt[i]  : 0.0f;
        }
        g_meta[roi] = make_int4(Kr, xmin, xmax, lv);
    }
}

// ---------------------------------------------------------------------------
// Kernel D: pooling. One warp per (roi, channel). grid (RSEL, BB, 32).
// ---------------------------------------------------------------------------
__global__ void __launch_bounds__(256)
pool_kernel(const float* __restrict__ f0,
            const float* __restrict__ f1,
            const float* __restrict__ f2,
            const float* __restrict__ f3,
            float* __restrict__ out)
{
    const int r = blockIdx.x, b = blockIdx.y;
    const int roi = b * RSEL + r;
    const int tid = threadIdx.x;
    const int warp = tid >> 5, lane = tid & 31;

    __shared__ float swx[MAXSPAN];
    __shared__ int   srows[MAXROWS];
    __shared__ float srwt[MAXROWS];
    __shared__ int4  smeta;

    if (tid < MAXSPAN)                          swx[tid] = g_wx[roi][tid];
    else if (tid < MAXSPAN + MAXROWS)           srows[tid - MAXSPAN] = g_rows[roi][tid - MAXSPAN];
    else if (tid < MAXSPAN + 2 * MAXROWS)       srwt[tid - MAXSPAN - MAXROWS] = g_rwt[roi][tid - MAXSPAN - MAXROWS];
    else if (tid == MAXSPAN + 2 * MAXROWS)      smeta = g_meta[roi];
    __syncthreads();

    const int Kr   = smeta.x;
    const int xmin = smeta.y;
    const int xmax = smeta.z;
    const int lv   = smeta.w;

    const int Hs[4] = {200, 100, 50, 25};
    const int H = Hs[lv], W = H;
    const float* fbase =
        (lv == 0 ? f0 : lv == 1 ? f1 : lv == 2 ? f2 : f3) + (size_t)b * CCH * H * W;

    const int c = blockIdx.z * 8 + warp;
    const float* cp = fbase + (size_t)c * H * W;

    const int x0 = xmin + lane;
    const int x1 = x0 + 32;
    const bool a0 = (x0 <= xmax);
    const bool a1 = (x1 <= xmax);
    const float w0 = a0 ? swx[lane] : 0.0f;
    const float w1 = a1 ? swx[lane + 32] : 0.0f;

    float acc = 0.0f;
    #pragma unroll 4
    for (int j = 0; j < Kr; j++) {
        const float* rp = cp + srows[j] * W;
        float s = 0.0f;
        if (a0) s = rp[x0] * w0;
        if (a1) s += rp[x1] * w1;
        acc += srwt[j] * s;
    }

    #pragma unroll
    for (int o = 16; o > 0; o >>= 1)
        acc += __shfl_xor_sync(0xffffffffu, acc, o);

    if (lane == 0)
        out[(size_t)roi * CCH + c] = acc * (1.0f / 196.0f);
}

// ---------------------------------------------------------------------------
extern "C" void kernel_launch(void* const* d_in, const int* in_sizes, int n_in,
                              void* d_out, int out_size)
{
    const float* boxes  = (const float*)d_in[0];
    const float* scores = (const float*)d_in[1];
    const float* f0     = (const float*)d_in[2];
    const float* f1     = (const float*)d_in[3];
    const float* f2     = (const float*)d_in[4];
    const float* f3     = (const float*)d_in[5];
    float* out = (float*)d_out;

    sort_kernel<<<BB, 320>>>(boxes, scores);
    iou_kernel<<<dim3(NWORDS, BB), 320>>>();
    nms_kernel<<<BB, 320>>>();
    pool_kernel<<<dim3(RSEL, BB, 32), 256>>>(f0, f1, f2, f3, out);
}